// round 11
// baseline (speedup 1.0000x reference)
#include <cuda_runtime.h>
#include <math.h>

#define NE   1024
#define NIN  64
#define HID  128
#define NOUT 64
#define ND   48      // Chebyshev nodes / coefficients per hidden unit
#define PS   8       // partner splits in k_chebF

// Scratch (__device__ globals per allocation-free rule)
__device__ float g_A  [NE * HID];   // A = x@W1a + b1, [i][h]
__device__ float g_B  [NE * HID];   // B = x@W1b,      [i][h]
__device__ float g_Bt [HID * NE];   // B transposed,   [h][i]
__device__ float g_F  [ND * HID];   // F_h at nodes,   [j][h] (atomicAdd target)
__device__ float g_C  [ND * HID];   // Chebyshev coeffs [k][h]
__device__ int   g_MaxI[HID];       // per-h max|A| as ordered int (atomicMax)

__device__ __forceinline__ float tanh_fast(float x) {
    float y;
    asm("tanh.approx.f32 %0, %1;" : "=f"(y) : "f"(x));
    return y;
}

// ---------------------------------------------------------------------------
// K1: projection. grid 256 x block 256 = (f-half, h), 4 rows per block.
// Emits A,B ([i][h]), Bt ([h][i]), per-h atomicMax|A|; zeros g_F (block 0).
// ---------------------------------------------------------------------------
__global__ void __launch_bounds__(256) k_proj(const float* __restrict__ x,
                                              const float* __restrict__ W1,
                                              const float* __restrict__ bias1) {
    const int tid = threadIdx.x;
    const int fh  = tid >> 7;        // which half of f-range
    const int h   = tid & 127;
    const int i0  = blockIdx.x * 4;

    // zero the F accumulator once per launch (atomicAdd target in k_chebF)
    if (blockIdx.x == 0)
        for (int k = tid; k < ND * HID; k += 256) g_F[k] = 0.f;

    __shared__ float sx[4][NIN];
    sx[tid >> 6][tid & 63] = x[i0 * NIN + tid];
    __syncthreads();

    float a[4], b[4];
    const float binit = (fh == 0) ? bias1[h] : 0.f;
#pragma unroll
    for (int r = 0; r < 4; r++) { a[r] = binit; b[r] = 0.f; }

    const int f0 = fh * 32;
#pragma unroll
    for (int ff = 0; ff < 32; ff++) {
        const int f = f0 + ff;
        const float w1a = W1[f * HID + h];
        const float w1b = W1[(NIN + f) * HID + h];
#pragma unroll
        for (int r = 0; r < 4; r++) {
            a[r] = fmaf(sx[r][f], w1a, a[r]);
            b[r] = fmaf(sx[r][f], w1b, b[r]);
        }
    }

    __shared__ float s_ab[8][HID];
    if (fh == 1) {
#pragma unroll
        for (int r = 0; r < 4; r++) {
            s_ab[r][h]     = a[r];
            s_ab[4 + r][h] = b[r];
        }
    }
    __syncthreads();
    if (fh == 0) {
        float m = 0.f;
#pragma unroll
        for (int r = 0; r < 4; r++) {
            const float av = a[r] + s_ab[r][h];
            const float bv = b[r] + s_ab[4 + r][h];
            const int i = i0 + r;
            g_A[i * HID + h] = av;
            g_B[i * HID + h] = bv;
            g_Bt[h * NE + i] = bv;
            m = fmaxf(m, fabsf(av));
        }
        atomicMax(&g_MaxI[h], __float_as_int(m));   // m>=0: int order == float order
    }
}

// ---------------------------------------------------------------------------
// K2: F_h(node_j) = sum_p tanh(node_j + B[p][h]), partial over 128 partners.
// grid = 128 h * PS = 1024 blocks, 128 threads. Warp w owns nodes [12w,12w+12).
// ---------------------------------------------------------------------------
__global__ void __launch_bounds__(128, 8) k_chebF(void) {
    const int bx   = blockIdx.x;
    const int h    = bx & 127;
    const int ps   = bx >> 7;
    const int t    = threadIdx.x;
    const int w    = t >> 5;
    const int lane = t & 31;

    const float r = fmaxf(__int_as_float(g_MaxI[h]), 1e-4f);

    float nodes[12];
#pragma unroll
    for (int jj = 0; jj < 12; jj++)
        nodes[jj] = r * cospif((w * 12 + jj + 0.5f) * (1.0f / ND));

    float part[12];
#pragma unroll
    for (int jj = 0; jj < 12; jj++) part[jj] = 0.f;

    const float* __restrict__ rowB = g_Bt + h * NE + ps * 128;
#pragma unroll
    for (int m = 0; m < 4; m++) {
        const float bv = rowB[m * 32 + lane];
#pragma unroll
        for (int jj = 0; jj < 12; jj++)
            part[jj] += tanh_fast(nodes[jj] + bv);
    }

#pragma unroll
    for (int jj = 0; jj < 12; jj++) {
#pragma unroll
        for (int d = 16; d; d >>= 1)
            part[jj] += __shfl_xor_sync(0xffffffffu, part[jj], d);
        if (lane == jj)
            atomicAdd(&g_F[(w * 12 + jj) * HID + h], part[jj]);
    }
}

// ---------------------------------------------------------------------------
// K3: DCT-II -> Chebyshev coefficients. grid = ND blocks (k), 128 threads (h).
// ---------------------------------------------------------------------------
__global__ void __launch_bounds__(128) k_chebC(void) {
    const int k = blockIdx.x;
    const int h = threadIdx.x;
    float sum = 0.f;
#pragma unroll 8
    for (int j = 0; j < ND; j++)
        sum = fmaf(g_F[j * HID + h], cospif((float)k * (j + 0.5f) * (1.0f / ND)), sum);
    g_C[k * HID + h] = sum * ((k == 0) ? (1.0f / ND) : (2.0f / ND));
}

// ---------------------------------------------------------------------------
// K4: Clenshaw eval + self-term + mean + fused W2 epilogue.
// grid = 256 blocks, 256 threads: half-block hg handles rows r0+2hg, r0+2hg+1.
// Epilogue: 1 output per thread, 4-way split accumulators.
// ---------------------------------------------------------------------------
__global__ void __launch_bounds__(256) k_evalout(const float* __restrict__ W2,
                                                 const float* __restrict__ b2,
                                                 float* __restrict__ out) {
    const int tid = threadIdx.x;
    const int hg  = tid >> 7;          // 0 or 1
    const int h   = tid & 127;
    const int r0  = blockIdx.x * 4;
    const int ra  = r0 + hg * 2;       // this half-block's first row

    const float rinv = 1.0f / fmaxf(__int_as_float(g_MaxI[h]), 1e-4f);

    const float A0 = g_A[(ra + 0) * HID + h];
    const float A1 = g_A[(ra + 1) * HID + h];
    const float t0 = A0 * rinv, t1 = A1 * rinv;        // in [-1,1]
    const float t0x2 = t0 + t0, t1x2 = t1 + t1;

    float p1_0 = 0.f, p2_0 = 0.f, p1_1 = 0.f, p2_1 = 0.f;
#pragma unroll
    for (int k = ND - 1; k >= 1; k--) {
        const float ak = g_C[k * HID + h];
        const float n0 = fmaf(t0x2, p1_0, ak - p2_0);
        const float n1 = fmaf(t1x2, p1_1, ak - p2_1);
        p2_0 = p1_0; p1_0 = n0;
        p2_1 = p1_1; p1_1 = n1;
    }
    const float a0  = g_C[h];
    const float inv = 1.0f / (float)(NE - 1);

    __shared__ float sacc[4][HID];
    {
        const float B0 = g_B[(ra + 0) * HID + h];
        const float B1 = g_B[(ra + 1) * HID + h];
        float F0 = fmaf(t0, p1_0, a0 - p2_0) - tanh_fast(A0 + B0);  // exclude p==i
        float F1 = fmaf(t1, p1_1, a0 - p2_1) - tanh_fast(A1 + B1);
        sacc[hg * 2 + 0][h] = F0 * inv;
        sacc[hg * 2 + 1][h] = F1 * inv;
    }
    __syncthreads();

    // Epilogue: 4*NOUT = 256 outputs, 256 threads -> 1 each; 4 accumulators.
    const int rr = tid >> 6;
    const int o  = tid & (NOUT - 1);
    float acc0 = 0.f, acc1 = 0.f, acc2 = 0.f, acc3 = 0.f;
#pragma unroll
    for (int hh = 0; hh < 32; hh++) {
        acc0 = fmaf(sacc[rr][hh],      W2[hh * NOUT + o],        acc0);
        acc1 = fmaf(sacc[rr][32 + hh], W2[(32 + hh) * NOUT + o], acc1);
        acc2 = fmaf(sacc[rr][64 + hh], W2[(64 + hh) * NOUT + o], acc2);
        acc3 = fmaf(sacc[rr][96 + hh], W2[(96 + hh) * NOUT + o], acc3);
    }
    out[(r0 + rr) * NOUT + o] = b2[o] + ((acc0 + acc1) + (acc2 + acc3));
}

// ---------------------------------------------------------------------------
extern "C" void kernel_launch(void* const* d_in, const int* in_sizes, int n_in,
                              void* d_out, int out_size) {
    const float* x  = (const float*)d_in[0];
    const float* W1 = (const float*)d_in[1];
    const float* b1 = (const float*)d_in[2];
    const float* W2 = (const float*)d_in[3];
    const float* b2 = (const float*)d_in[4];
    float* out = (float*)d_out;

    k_proj<<<NE / 4, 256>>>(x, W1, b1);
    k_chebF<<<HID * PS, 128>>>();
    k_chebC<<<ND, 128>>>();
    k_evalout<<<NE / 4, 256>>>(W2, b2, out);
}

// round 12
// speedup vs baseline: 1.0667x; 1.0667x over previous
#include <cuda_runtime.h>
#include <math.h>

#define NE   1024
#define NIN  64
#define HID  128
#define NOUT 64
#define ND   48      // Chebyshev nodes / coefficients per hidden unit
#define PS   8       // partner splits in k_chebF

// Scratch (__device__ globals per allocation-free rule)
__device__ float g_A  [NE * HID];   // A = x@W1a + b1, [i][h]
__device__ float g_B  [NE * HID];   // B = x@W1b,      [i][h]
__device__ float g_Bt [HID * NE];   // B transposed,   [h][i]
__device__ float g_F  [ND * HID];   // F_h at nodes,   [j][h] (atomicAdd target)
__device__ float g_C  [ND * HID];   // Chebyshev coeffs [k][h]
__device__ int   g_MaxI[HID];       // per-h max|A| as ordered int (atomicMax)

__device__ __forceinline__ float tanh_fast(float x) {
    float y;
    asm("tanh.approx.f32 %0, %1;" : "=f"(y) : "f"(x));
    return y;
}

// ---------------------------------------------------------------------------
// K1: projection. grid 256 x block 256 = (f-half, h), 4 rows per block.
// Emits A,B ([i][h]), Bt ([h][i]), per-h atomicMax|A|; zeros g_F (block 0).
// ---------------------------------------------------------------------------
__global__ void __launch_bounds__(256) k_proj(const float* __restrict__ x,
                                              const float* __restrict__ W1,
                                              const float* __restrict__ bias1) {
    const int tid = threadIdx.x;
    const int fh  = tid >> 7;        // which half of f-range
    const int h   = tid & 127;
    const int i0  = blockIdx.x * 4;

    // zero the F accumulator once per launch (atomicAdd target in k_chebF)
    if (blockIdx.x == 0)
        for (int k = tid; k < ND * HID; k += 256) g_F[k] = 0.f;

    __shared__ float sx[4][NIN];
    sx[tid >> 6][tid & 63] = x[i0 * NIN + tid];
    __syncthreads();

    float a[4], b[4];
    const float binit = (fh == 0) ? bias1[h] : 0.f;
#pragma unroll
    for (int r = 0; r < 4; r++) { a[r] = binit; b[r] = 0.f; }

    const int f0 = fh * 32;
#pragma unroll
    for (int ff = 0; ff < 32; ff++) {
        const int f = f0 + ff;
        const float w1a = W1[f * HID + h];
        const float w1b = W1[(NIN + f) * HID + h];
#pragma unroll
        for (int r = 0; r < 4; r++) {
            a[r] = fmaf(sx[r][f], w1a, a[r]);
            b[r] = fmaf(sx[r][f], w1b, b[r]);
        }
    }

    __shared__ float s_ab[8][HID];
    if (fh == 1) {
#pragma unroll
        for (int r = 0; r < 4; r++) {
            s_ab[r][h]     = a[r];
            s_ab[4 + r][h] = b[r];
        }
    }
    __syncthreads();
    if (fh == 0) {
        float m = 0.f;
#pragma unroll
        for (int r = 0; r < 4; r++) {
            const float av = a[r] + s_ab[r][h];
            const float bv = b[r] + s_ab[4 + r][h];
            const int i = i0 + r;
            g_A[i * HID + h] = av;
            g_B[i * HID + h] = bv;
            g_Bt[h * NE + i] = bv;
            m = fmaxf(m, fabsf(av));
        }
        atomicMax(&g_MaxI[h], __float_as_int(m));   // m>=0: int order == float order
    }
}

// ---------------------------------------------------------------------------
// K2: F_h(node_j) = sum_p tanh(node_j + B[p][h]), partial over 128 partners.
// grid = 128 h * PS = 1024 blocks, 128 threads. Warp w owns nodes [12w,12w+12).
// ---------------------------------------------------------------------------
__global__ void __launch_bounds__(128, 8) k_chebF(void) {
    const int bx   = blockIdx.x;
    const int h    = bx & 127;
    const int ps   = bx >> 7;
    const int t    = threadIdx.x;
    const int w    = t >> 5;
    const int lane = t & 31;

    const float r = fmaxf(__int_as_float(g_MaxI[h]), 1e-4f);

    float nodes[12];
#pragma unroll
    for (int jj = 0; jj < 12; jj++)
        nodes[jj] = r * cospif((w * 12 + jj + 0.5f) * (1.0f / ND));

    float part[12];
#pragma unroll
    for (int jj = 0; jj < 12; jj++) part[jj] = 0.f;

    const float* __restrict__ rowB = g_Bt + h * NE + ps * 128;
#pragma unroll
    for (int m = 0; m < 4; m++) {
        const float bv = rowB[m * 32 + lane];
#pragma unroll
        for (int jj = 0; jj < 12; jj++)
            part[jj] += tanh_fast(nodes[jj] + bv);
    }

#pragma unroll
    for (int jj = 0; jj < 12; jj++) {
#pragma unroll
        for (int d = 16; d; d >>= 1)
            part[jj] += __shfl_xor_sync(0xffffffffu, part[jj], d);
        if (lane == jj)
            atomicAdd(&g_F[(w * 12 + jj) * HID + h], part[jj]);
    }
}

// ---------------------------------------------------------------------------
// K3: DCT-II -> Chebyshev coefficients. grid = ND blocks (k), 128 threads (h).
// ---------------------------------------------------------------------------
__global__ void __launch_bounds__(128) k_chebC(void) {
    const int k = blockIdx.x;
    const int h = threadIdx.x;
    float sum = 0.f;
#pragma unroll 8
    for (int j = 0; j < ND; j++)
        sum = fmaf(g_F[j * HID + h], cospif((float)k * (j + 0.5f) * (1.0f / ND)), sum);
    g_C[k * HID + h] = sum * ((k == 0) ? (1.0f / ND) : (2.0f / ND));
}

// ---------------------------------------------------------------------------
// K4: Clenshaw eval + self-term + mean + fused W2 epilogue.
// grid = 256 blocks, 256 threads: half-block hg handles rows r0+2hg, r0+2hg+1.
// Coefficients preloaded into a register array (batched LDGs, MLP~48) so the
// recurrence is pure FMA on registers — this is what R10 got implicitly via
// regs=128 and R11 lost (regs=32 -> serialized loads).
// ---------------------------------------------------------------------------
__global__ void __launch_bounds__(256) k_evalout(const float* __restrict__ W2,
                                                 const float* __restrict__ b2,
                                                 float* __restrict__ out) {
    const int tid = threadIdx.x;
    const int hg  = tid >> 7;          // 0 or 1
    const int h   = tid & 127;
    const int r0  = blockIdx.x * 4;
    const int ra  = r0 + hg * 2;       // this half-block's first row

    // ---- batched coefficient preload (independent LDGs) ----
    float creg[ND];
#pragma unroll
    for (int k = 0; k < ND; k++)
        creg[k] = g_C[k * HID + h];

    const float rinv = 1.0f / fmaxf(__int_as_float(g_MaxI[h]), 1e-4f);

    const float A0 = g_A[(ra + 0) * HID + h];
    const float A1 = g_A[(ra + 1) * HID + h];
    const float B0 = g_B[(ra + 0) * HID + h];
    const float B1 = g_B[(ra + 1) * HID + h];

    const float t0 = A0 * rinv, t1 = A1 * rinv;        // in [-1,1]
    const float t0x2 = t0 + t0, t1x2 = t1 + t1;

    float p1_0 = 0.f, p2_0 = 0.f, p1_1 = 0.f, p2_1 = 0.f;
#pragma unroll
    for (int k = ND - 1; k >= 1; k--) {
        const float ak = creg[k];
        const float n0 = fmaf(t0x2, p1_0, ak - p2_0);
        const float n1 = fmaf(t1x2, p1_1, ak - p2_1);
        p2_0 = p1_0; p1_0 = n0;
        p2_1 = p1_1; p1_1 = n1;
    }
    const float inv = 1.0f / (float)(NE - 1);

    __shared__ float sacc[4][HID];
    {
        float F0 = fmaf(t0, p1_0, creg[0] - p2_0) - tanh_fast(A0 + B0);  // excl p==i
        float F1 = fmaf(t1, p1_1, creg[0] - p2_1) - tanh_fast(A1 + B1);
        sacc[hg * 2 + 0][h] = F0 * inv;
        sacc[hg * 2 + 1][h] = F1 * inv;
    }
    __syncthreads();

    // Epilogue: 4*NOUT = 256 outputs, 256 threads -> 1 each; 4 accumulators.
    const int rr = tid >> 6;
    const int o  = tid & (NOUT - 1);
    float acc0 = 0.f, acc1 = 0.f, acc2 = 0.f, acc3 = 0.f;
#pragma unroll
    for (int hh = 0; hh < 32; hh++) {
        acc0 = fmaf(sacc[rr][hh],      W2[hh * NOUT + o],        acc0);
        acc1 = fmaf(sacc[rr][32 + hh], W2[(32 + hh) * NOUT + o], acc1);
        acc2 = fmaf(sacc[rr][64 + hh], W2[(64 + hh) * NOUT + o], acc2);
        acc3 = fmaf(sacc[rr][96 + hh], W2[(96 + hh) * NOUT + o], acc3);
    }
    out[(r0 + rr) * NOUT + o] = b2[o] + ((acc0 + acc1) + (acc2 + acc3));
}

// ---------------------------------------------------------------------------
extern "C" void kernel_launch(void* const* d_in, const int* in_sizes, int n_in,
                              void* d_out, int out_size) {
    const float* x  = (const float*)d_in[0];
    const float* W1 = (const float*)d_in[1];
    const float* b1 = (const float*)d_in[2];
    const float* W2 = (const float*)d_in[3];
    const float* b2 = (const float*)d_in[4];
    float* out = (float*)d_out;

    k_proj<<<NE / 4, 256>>>(x, W1, b1);
    k_chebF<<<HID * PS, 128>>>();
    k_chebC<<<ND, 128>>>();
    k_evalout<<<NE / 4, 256>>>(W2, b2, out);
}

// round 13
// speedup vs baseline: 1.5225x; 1.4274x over previous
#include <cuda_runtime.h>
#include <math.h>

#define NE    1024
#define NIN   64
#define HID   128
#define NOUT  64
#define ND    48
#define NBLK  128      // persistent grid; must be <= SM count (148) for co-residency

// Scratch (__device__ globals per allocation-free rule)
__device__ float g_A [NE * HID];    // A = x@W1a + b1, [i][h]
__device__ float g_B [NE * HID];    // B = x@W1b,      [i][h]
__device__ float g_Bt[HID * NE];    // B transposed,   [h][i]
__device__ float g_C [ND * HID];    // Chebyshev coeffs [k][h]
__device__ int   g_MaxI[HID];       // per-h max|A| (ordered-int atomicMax; idempotent)
__device__ unsigned g_barcnt = 0;   // barrier arrival counter (returns to 0 each use)
__device__ unsigned g_barph  = 0;   // barrier phase (monotonic across graph replays)

__device__ __forceinline__ float tanh_fast(float x) {
    float y;
    asm("tanh.approx.f32 %0, %1;" : "=f"(y) : "f"(x));
    return y;
}

// Grid-wide barrier: all NBLK blocks co-resident (NBLK <= #SM). Data written
// before arrival is fenced; release via monotonic phase counter (replay-safe).
__device__ __forceinline__ void grid_barrier(unsigned target) {
    __syncthreads();
    if (threadIdx.x == 0) {
        __threadfence();
        const unsigned old = atomicAdd(&g_barcnt, 1);
        if (old == NBLK - 1) {
            g_barcnt = 0;
            __threadfence();
            atomicAdd(&g_barph, 1);
        } else {
            while ((int)(*(volatile unsigned*)&g_barph - target) < 0)
                __nanosleep(32);
        }
        __threadfence();
    }
    __syncthreads();
}

// Overlapping smem for the three phases
struct SmemProj { float sx[8][NIN]; float s_ab[16][HID]; };       // 10.25 KB
struct SmemA    { float nodes[ND]; float red[8][ND]; float F[ND]; }; // ~1.9 KB
struct SmemB    { float sacc[8][HID]; };                          // 4 KB
union SmemU { SmemProj proj; SmemA pa; SmemB pb; };

__global__ void __launch_bounds__(256, 1)
k_all(const float* __restrict__ x,  const float* __restrict__ W1,
      const float* __restrict__ b1, const float* __restrict__ W2,
      const float* __restrict__ b2, float* __restrict__ out) {
    const int tid = threadIdx.x;
    const int blk = blockIdx.x;

    __shared__ SmemU u;
    __shared__ float sW2[HID * NOUT];   // 32 KB
    __shared__ unsigned s_ph0;

    // read barrier phase BEFORE any arrival (safe: barrier can't release
    // until this block arrives, so the value is launch-stable)
    if (tid == 0) s_ph0 = *(volatile unsigned*)&g_barph;

    // stage W2 into smem (overlaps proj compute)
    {
        const float4* src = reinterpret_cast<const float4*>(W2);
        float4*       dst = reinterpret_cast<float4*>(sW2);
#pragma unroll
        for (int k = 0; k < 8; k++) dst[k * 256 + tid] = src[k * 256 + tid];
    }

    // ---------------- Phase 1: projection (8 rows per block) ----------------
    {
        const int i0 = blk * 8;
        // load 8 x rows (512 floats)
        u.proj.sx[tid >> 6][tid & 63]                 = x[i0 * NIN + tid];
        u.proj.sx[(tid + 256) >> 6][(tid + 256) & 63] = x[i0 * NIN + tid + 256];
        __syncthreads();

        const int fh = tid >> 7;         // f-half
        const int h  = tid & 127;
        const float binit = (fh == 0) ? b1[h] : 0.f;
        float a[8], b[8];
#pragma unroll
        for (int r = 0; r < 8; r++) { a[r] = binit; b[r] = 0.f; }

        const int f0 = fh * 32;
#pragma unroll
        for (int ff = 0; ff < 32; ff++) {
            const int f = f0 + ff;
            const float w1a = W1[f * HID + h];
            const float w1b = W1[(NIN + f) * HID + h];
#pragma unroll
            for (int r = 0; r < 8; r++) {
                a[r] = fmaf(u.proj.sx[r][f], w1a, a[r]);
                b[r] = fmaf(u.proj.sx[r][f], w1b, b[r]);
            }
        }
        if (fh == 1) {
#pragma unroll
            for (int r = 0; r < 8; r++) {
                u.proj.s_ab[r][h]     = a[r];
                u.proj.s_ab[8 + r][h] = b[r];
            }
        }
        __syncthreads();
        if (fh == 0) {
            float m = 0.f;
#pragma unroll
            for (int r = 0; r < 8; r++) {
                const float av = a[r] + u.proj.s_ab[r][h];
                const float bv = b[r] + u.proj.s_ab[8 + r][h];
                const int i = i0 + r;
                g_A[i * HID + h] = av;
                g_B[i * HID + h] = bv;
                g_Bt[h * NE + i] = bv;
                m = fmaxf(m, fabsf(av));
            }
            atomicMax(&g_MaxI[h], __float_as_int(m));  // m>=0: int order == float order
        }
    }

    const unsigned ph0 = s_ph0;
    grid_barrier(ph0 + 1);   // all A/B/Bt/MaxI visible

    // ------- Phase 2: F_h at ND Chebyshev nodes + DCT, one block per h -------
    {
        const int h = blk;
        const float r = fmaxf(__int_as_float(g_MaxI[h]), 1e-4f);
        if (tid < ND)
            u.pa.nodes[tid] = r * cospif((tid + 0.5f) * (1.0f / ND));
        __syncthreads();

        float part[ND];
#pragma unroll
        for (int j = 0; j < ND; j++) part[j] = 0.f;

        const float* __restrict__ rowB = g_Bt + h * NE;
#pragma unroll
        for (int m = 0; m < 4; m++) {
            const float bv = rowB[m * 256 + tid];
#pragma unroll
            for (int j = 0; j < ND; j++)
                part[j] += tanh_fast(u.pa.nodes[j] + bv);
        }

        const int w = tid >> 5, lane = tid & 31;
#pragma unroll
        for (int j = 0; j < ND; j++) {
            float v = part[j];
#pragma unroll
            for (int d = 16; d; d >>= 1)
                v += __shfl_xor_sync(0xffffffffu, v, d);
            if (lane == 0) u.pa.red[w][j] = v;
        }
        __syncthreads();
        if (tid < ND) {
            float F = 0.f;
#pragma unroll
            for (int w8 = 0; w8 < 8; w8++) F += u.pa.red[w8][tid];
            u.pa.F[tid] = F;
        }
        __syncthreads();
        if (tid < ND) {
            const int k = tid;
            float s = 0.f;
#pragma unroll 8
            for (int j = 0; j < ND; j++)
                s = fmaf(u.pa.F[j], cospif((float)k * (j + 0.5f) * (1.0f / ND)), s);
            g_C[k * HID + h] = s * ((k == 0) ? (1.0f / ND) : (2.0f / ND));
        }
    }

    grid_barrier(ph0 + 2);   // all coefficients visible

    // ------ Phase 3: Clenshaw + self-term + mean + W2 epilogue (8 rows) ------
    {
        const int hg = tid >> 7;          // half-block: 4 rows each
        const int h  = tid & 127;
        const int ra = blk * 8 + hg * 4;

        float creg[ND];                   // batched preload (R12 lesson: MLP~48)
#pragma unroll
        for (int k = 0; k < ND; k++) creg[k] = g_C[k * HID + h];

        const float rinv = 1.0f / fmaxf(__int_as_float(g_MaxI[h]), 1e-4f);

        float Av[4], Bv[4], tt[4], t2[4], p1[4], p2[4];
#pragma unroll
        for (int q = 0; q < 4; q++) {
            Av[q] = g_A[(ra + q) * HID + h];
            Bv[q] = g_B[(ra + q) * HID + h];
            tt[q] = Av[q] * rinv;
            t2[q] = tt[q] + tt[q];
            p1[q] = 0.f; p2[q] = 0.f;
        }
#pragma unroll
        for (int k = ND - 1; k >= 1; k--) {
            const float ak = creg[k];
#pragma unroll
            for (int q = 0; q < 4; q++) {
                const float n = fmaf(t2[q], p1[q], ak - p2[q]);
                p2[q] = p1[q]; p1[q] = n;
            }
        }
        const float inv = 1.0f / (float)(NE - 1);
#pragma unroll
        for (int q = 0; q < 4; q++) {
            float F = fmaf(tt[q], p1[q], creg[0] - p2[q]);
            F -= tanh_fast(Av[q] + Bv[q]);          // exclude p == i
            u.pb.sacc[hg * 4 + q][h] = F * inv;
        }
        __syncthreads();

        // 512 outputs (8 rows x 64), 256 threads -> 2 each, 4-split accums
#pragma unroll
        for (int e = 0; e < 2; e++) {
            const int idx = e * 256 + tid;
            const int rr  = idx >> 6;
            const int o   = idx & (NOUT - 1);
            float a0 = 0.f, a1 = 0.f, a2 = 0.f, a3 = 0.f;
#pragma unroll
            for (int hh = 0; hh < 32; hh++) {
                a0 = fmaf(u.pb.sacc[rr][hh],      sW2[hh * NOUT + o],        a0);
                a1 = fmaf(u.pb.sacc[rr][32 + hh], sW2[(32 + hh) * NOUT + o], a1);
                a2 = fmaf(u.pb.sacc[rr][64 + hh], sW2[(64 + hh) * NOUT + o], a2);
                a3 = fmaf(u.pb.sacc[rr][96 + hh], sW2[(96 + hh) * NOUT + o], a3);
            }
            out[(blk * 8 + rr) * NOUT + o] = b2[o] + ((a0 + a1) + (a2 + a3));
        }
    }
}

// ---------------------------------------------------------------------------
extern "C" void kernel_launch(void* const* d_in, const int* in_sizes, int n_in,
                              void* d_out, int out_size) {
    const float* x  = (const float*)d_in[0];
    const float* W1 = (const float*)d_in[1];
    const float* b1 = (const float*)d_in[2];
    const float* W2 = (const float*)d_in[3];
    const float* b2 = (const float*)d_in[4];
    float* out = (float*)d_out;

    k_all<<<NBLK, 256>>>(x, W1, b1, W2, b2, out);
}